// round 8
// baseline (speedup 1.0000x reference)
#include <cuda_runtime.h>
#include <cuda_fp16.h>

#define BATCH   256
#define IN_DIM  65536
#define OUT_DIM 65536

#define NB_T 2048   // transpose tiles: (IN/128) x (B/64)
#define NB_C 256
#define NB_I 512
#define PF_DIST 896 // prefetch ~one wave ahead

// ---------------- device scratch ----------------------------------------
__device__ float4 g_coef[OUT_DIM];                             // 1 MB
__device__ __align__(16) __half g_xth[(size_t)IN_DIM * BATCH]; // 32 MB
__device__ int    g_idx[2 * OUT_DIM];                          // 512 KB

// ---------------- fused prep: transpose + coef + idx --------------------
__global__ __launch_bounds__(256) void prep_kernel(const float* __restrict__ x,
                                                   const float* __restrict__ wts,
                                                   const void*  __restrict__ idxraw) {
    __shared__ float t[4][64][33];
    int bx  = blockIdx.x;
    int tid = threadIdx.x;

    if (bx < NB_T) {
        // L2 prefetch for the tile ~one wave ahead (TMA queue, bypasses
        // SM MSHR limit -> consumers hit L2 instead of raw DRAM latency)
        int pfb = bx + PF_DIST;
        if (pfb < NB_T && tid < 64) {
            int it2 = pfb & 511, bt2 = pfb >> 9;
            const char* p = (const char*)(x + (size_t)(bt2 * 64 + tid) * IN_DIM + it2 * 128);
            asm volatile("cp.async.bulk.prefetch.L2.global [%0], %1;"
                         :: "l"(p), "r"(512));
        }

        // tile: 128 inputs x 64 batches; 8 float4 loads in flight
        int it = bx & 511, bt = bx >> 9;
        int i0 = it * 128, b0 = bt * 64;
        int tx = tid & 7, ty = tid >> 3;

        const float4* r0 = (const float4*)(x + (size_t)(b0 + ty)      * IN_DIM + i0);
        const float4* r1 = (const float4*)(x + (size_t)(b0 + 32 + ty) * IN_DIM + i0);
        float4 v0[4], v1[4];
        #pragma unroll
        for (int h = 0; h < 4; h++) {
            v0[h] = __ldcs(r0 + tx + 8 * h);
            v1[h] = __ldcs(r1 + tx + 8 * h);
        }
        #pragma unroll
        for (int h = 0; h < 4; h++) {
            t[h][ty   ][tx*4+0]=v0[h].x; t[h][ty   ][tx*4+1]=v0[h].y;
            t[h][ty   ][tx*4+2]=v0[h].z; t[h][ty   ][tx*4+3]=v0[h].w;
            t[h][ty+32][tx*4+0]=v1[h].x; t[h][ty+32][tx*4+1]=v1[h].y;
            t[h][ty+32][tx*4+2]=v1[h].z; t[h][ty+32][tx*4+3]=v1[h].w;
        }
        __syncthreads();
        #pragma unroll
        for (int h = 0; h < 4; h++) {
            union { uint4 u; __half2 hh[4]; } pk;
            #pragma unroll
            for (int k = 0; k < 4; k++)
                pk.hh[k] = __floats2half2_rn(t[h][8*tx + 2*k][ty], t[h][8*tx + 2*k + 1][ty]);
            *(uint4*)(g_xth + (size_t)(i0 + 32*h + ty) * BATCH + b0 + 8*tx) = pk.u;
        }
    } else if (bx < NB_T + NB_C) {
        // softmax -> bilinear coefficients
        int o = (bx - NB_T) * 256 + tid;
        float p[16];
        const float4* w4 = (const float4*)(wts + (size_t)o * 16);
        float4 q0 = w4[0], q1 = w4[1], q2 = w4[2], q3 = w4[3];
        p[0]=q0.x; p[1]=q0.y; p[2]=q0.z; p[3]=q0.w;
        p[4]=q1.x; p[5]=q1.y; p[6]=q1.z; p[7]=q1.w;
        p[8]=q2.x; p[9]=q2.y; p[10]=q2.z; p[11]=q2.w;
        p[12]=q3.x; p[13]=q3.y; p[14]=q3.z; p[15]=q3.w;
        float m = p[0];
        #pragma unroll
        for (int i = 1; i < 16; i++) m = fmaxf(m, p[i]);
        float s = 0.f;
        #pragma unroll
        for (int i = 0; i < 16; i++) { p[i] = __expf(p[i] - m); s += p[i]; }
        float inv = 1.0f / s;
        #pragma unroll
        for (int i = 0; i < 16; i++) p[i] *= inv;
        float4 c;
        c.x = p[8]+p[9]+p[10]+p[11]+p[12]+p[13]+p[14]+p[15];
        c.y = p[2]+p[3]+p[6]+p[7]-p[8]-p[9]-p[12]-p[13];
        c.z = p[4]+p[5]+p[6]+p[7]-p[8]-p[9]-p[10]-p[11];
        c.w = p[1]-p[2]-p[4]-2.f*p[6]-p[7]+p[8]+2.f*p[9]+p[11]+p[13]-p[14];
        g_coef[o] = c;
    } else {
        __shared__ int s64;
        if (tid == 0) {
            const long long* p = (const long long*)idxraw;
            int is64 = 1;
            #pragma unroll 1
            for (int j = 0; j < 64; j++) {
                long long v = p[j];
                if (v < 0 || v >= IN_DIM) { is64 = 0; break; }
            }
            s64 = is64;
        }
        __syncthreads();
        int i = (bx - NB_T - NB_C) * 256 + tid;
        g_idx[i] = s64 ? (int)((const long long*)idxraw)[i]
                       : ((const int*)idxraw)[i];
    }
}

// ---------------- main: 64 neurons x 256 batches per 512-thread block ---
// 16 warps x 4 neurons; 8 LDG.128 in flight per lane (full 512B rows).
// smem swizzle: store col=(n+l)&63 (banks n+l bijective), read
// col=(l+(b>>3))&63 / +32 (banks l+const bijective). One barrier/block.
__global__ __launch_bounds__(512, 2) void logic_main_kernel(float* __restrict__ out) {
    __shared__ float s[BATCH * 64];           // 64 KB
    int tid = threadIdx.x;
    int w = tid >> 5;                         // 0..15
    int l = tid & 31;
    int ob = blockIdx.x * 64;
    int nb = w * 4;

    const char* base = (const char*)g_xth;
    unsigned lane16 = (unsigned)l * 16u;
    unsigned offa[4], offb[4];
    #pragma unroll
    for (int c = 0; c < 4; c++) {
        offa[c] = (unsigned)__ldg(&g_idx[ob + nb + c])           * 512u + lane16;
        offb[c] = (unsigned)__ldg(&g_idx[OUT_DIM + ob + nb + c]) * 512u + lane16;
    }
    uint4 va[4], vb[4];
    #pragma unroll
    for (int c = 0; c < 4; c++) {
        va[c] = *(const uint4*)(base + offa[c]);
        vb[c] = *(const uint4*)(base + offb[c]);
    }

    #pragma unroll
    for (int c = 0; c < 4; c++) {
        float4 cf = __ldg(&g_coef[ob + nb + c]);
        union { uint4 u; __half2 h[4]; } A, Bv;
        A.u = va[c]; Bv.u = vb[c];
        int col = (nb + c + l) & 63;
        #pragma unroll
        for (int k = 0; k < 4; k++) {
            float2 a = __half22float2(A.h[k]);
            float2 b = __half22float2(Bv.h[k]);
            int bb = 8 * l + 2 * k;
            s[bb * 64 + col]       = fmaf(fmaf(cf.w, b.x, cf.y), a.x, fmaf(cf.z, b.x, cf.x));
            s[(bb + 1) * 64 + col] = fmaf(fmaf(cf.w, b.y, cf.y), a.y, fmaf(cf.z, b.y, cf.x));
        }
    }
    __syncthreads();

    // warp w writes batch rows 16w..16w+15; 2x 128B-coalesced stores/row
    #pragma unroll
    for (int j = 0; j < 16; j++) {
        int bb = w * 16 + j;
        int c0 = (l + (bb >> 3)) & 63;
        int c1 = (c0 + 32) & 63;
        __stcs(out + (size_t)bb * OUT_DIM + ob + l,      s[bb * 64 + c0]);
        __stcs(out + (size_t)bb * OUT_DIM + ob + 32 + l, s[bb * 64 + c1]);
    }
}

// ---------------- launch ------------------------------------------------
extern "C" void kernel_launch(void* const* d_in, const int* in_sizes, int n_in,
                              void* d_out, int out_size) {
    const float* x   = (const float*)d_in[0];
    const float* wts = (const float*)d_in[1];
    const void*  idx = d_in[2];
    float* out = (float*)d_out;

    prep_kernel<<<NB_T + NB_C + NB_I, 256>>>(x, wts, idx);
    logic_main_kernel<<<OUT_DIM / 64, 512>>>(out);
}